// round 1
// baseline (speedup 1.0000x reference)
#include <cuda_runtime.h>

#define NN 16384
#define D 64
#define TITER 4
#define SPAD 32   // pad the 64 column-sum accumulators across L2 slices

// Scratch (allocation-free rule: __device__ globals)
__device__ float g_pos[NN];
__device__ float g_neg[NN];
__device__ float g_ab[2 * D];            // a = W3*relu(w4), b = W3*relu(-w4)
__device__ float g_u[2][NN * D];         // ping-pong u buffers (4 MB each)
__device__ float g_sums[TITER][D * SPAD];// s1..s4 column sums (padded)

// ---------------------------------------------------------------------------
// k_pre: zero the atomic accumulators (must happen inside the graph every
// replay) and precompute a,b vectors. 1 block x 256 threads.
// ---------------------------------------------------------------------------
__global__ void k_pre(const float* __restrict__ W3, const float* __restrict__ w4) {
    int t = threadIdx.x;
    float* s = (float*)g_sums;
    for (int i = t; i < TITER * D * SPAD; i += blockDim.x) s[i] = 0.f;
    if (t < D) {
        float a = 0.f, b = 0.f;
#pragma unroll
        for (int k = 0; k < D; k++) {
            float w = w4[k];
            float W = W3[t * D + k];
            a = fmaf(W, fmaxf(w, 0.f), a);
            b = fmaf(W, fmaxf(-w, 0.f), b);
        }
        g_ab[t]     = a;
        g_ab[D + t] = b;
    }
}

// ---------------------------------------------------------------------------
// k_rowsum: pos[i] = sum_j relu(g[i][j]), neg[i] = sum_j relu(-g[i][j]).
// One block per row (64 KB/row), float4 streaming loads (no reuse -> .cs).
// This is THE memory-bound kernel: 1.074 GB single pass.
// ---------------------------------------------------------------------------
__global__ void k_rowsum(const float* __restrict__ graph) {
    int row = blockIdx.x;
    const float4* g = reinterpret_cast<const float4*>(graph + (size_t)row * NN);
    float p = 0.f, n = 0.f;
#pragma unroll 4
    for (int i = threadIdx.x; i < NN / 4; i += 256) {
        float4 v = __ldcs(g + i);
        p += fmaxf(v.x, 0.f) + fmaxf(v.y, 0.f) + fmaxf(v.z, 0.f) + fmaxf(v.w, 0.f);
        n += fmaxf(-v.x, 0.f) + fmaxf(-v.y, 0.f) + fmaxf(-v.z, 0.f) + fmaxf(-v.w, 0.f);
    }
#pragma unroll
    for (int o = 16; o; o >>= 1) {
        p += __shfl_xor_sync(0xffffffffu, p, o);
        n += __shfl_xor_sync(0xffffffffu, n, o);
    }
    __shared__ float sp[8], sn[8];
    int lane = threadIdx.x & 31, w = threadIdx.x >> 5;
    if (lane == 0) { sp[w] = p; sn[w] = n; }
    __syncthreads();
    if (threadIdx.x == 0) {
        float P = 0.f, Q = 0.f;
#pragma unroll
        for (int i = 0; i < 8; i++) { P += sp[i]; Q += sn[i]; }
        g_pos[row] = P;
        g_neg[row] = Q;
    }
}

// ---------------------------------------------------------------------------
// k_iter: one message-passing step.
//   u_new[i,d] = relu( base[i,d] + sum_k W2[d,k]*(s[k] - u[i,k]) )
//   base[i,d]  = x[i]*w1[d] + pos[i]*a[d] + neg[i]*b[d]   (recomputed, cheap)
// Also accumulates column sums of u_new into g_sums[os].
// blockDim (64,8); each block handles 64 rows (8 tiles of 8).
// FIRST=true => u=0, s=0 => u1 = relu(base) (skip the GEMV entirely).
// ---------------------------------------------------------------------------
template <bool FIRST>
__global__ void k_iter(int ib, int ob, int is, int os,
                       const int* __restrict__ s_mask,
                       const float* __restrict__ w1,
                       const float* __restrict__ W2) {
    __shared__ float sW2T[D * 65];   // transposed W2, stride 65 (bank-conflict-free)
    __shared__ float sdiff[8][D];
    __shared__ float svec[4 * D];    // w1 | a | b | s_prev
    __shared__ float sred[8][D];

    const int tx = threadIdx.x;      // 0..63 = output dim d
    const int ty = threadIdx.y;      // 0..7  = row within tile
    const int tid = ty * D + tx;

    if (!FIRST) {
        // W2 row-major [d][k] -> sW2T[k*65 + d]
        for (int i = tid; i < D * D; i += 8 * D) {
            int d = i >> 6, k = i & (D - 1);
            sW2T[k * 65 + d] = W2[i];
        }
    }
    if (ty == 0) {
        svec[tx]         = w1[tx];
        svec[D + tx]     = g_ab[tx];
        svec[2 * D + tx] = g_ab[D + tx];
        svec[3 * D + tx] = FIRST ? 0.f : g_sums[is][tx * SPAD];
    }
    __syncthreads();

    const float* u_in  = g_u[ib];
    float*       u_out = g_u[ob];
    const int row0 = blockIdx.x * 64;

    float s_acc = 0.f;
    for (int tile = 0; tile < 8; tile++) {
        int row = row0 + tile * 8 + ty;
        float acc = 0.f;
        if (!FIRST) {
            sdiff[ty][tx] = svec[3 * D + tx] - u_in[row * D + tx];
            __syncthreads();
#pragma unroll
            for (int k = 0; k < D; k++)
                acc = fmaf(sW2T[k * 65 + tx], sdiff[ty][k], acc);
        }
        float base = (float)s_mask[row] * svec[tx]
                   + g_pos[row] * svec[D + tx]
                   + g_neg[row] * svec[2 * D + tx];
        float un = fmaxf(base + acc, 0.f);
        u_out[row * D + tx] = un;
        s_acc += un;
        if (!FIRST) __syncthreads();
    }

    // per-block column-sum reduce + one atomic per dim (256 atomics/address)
    sred[ty][tx] = s_acc;
    __syncthreads();
    if (ty == 0) {
        float tot = 0.f;
#pragma unroll
        for (int r = 0; r < 8; r++) tot += sred[r][tx];
        atomicAdd(&g_sums[os][tx * SPAD], tot);
    }
}

// ---------------------------------------------------------------------------
// k_final: out = relu(cat(W6 @ s_final, W7 @ u[v])) . w5    (1 block, 128 thr)
// v read device-side (works for int32 or int64 harness encoding of 123).
// ---------------------------------------------------------------------------
__global__ void k_final(int ib, int isum,
                        const int* __restrict__ v_ptr,
                        const float* __restrict__ W6,
                        const float* __restrict__ W7,
                        const float* __restrict__ w5,
                        float* __restrict__ out) {
    __shared__ float part[128];
    int t = threadIdx.x;
    int v = v_ptr[0];
    const float* u_fin = g_u[ib];
    float h;
    if (t < D) {
        float acc = 0.f;
#pragma unroll
        for (int k = 0; k < D; k++)
            acc = fmaf(W6[t * D + k], g_sums[isum][k * SPAD], acc);
        h = fmaxf(acc, 0.f) * w5[t];
    } else {
        int d = t - D;
        float acc = 0.f;
#pragma unroll
        for (int k = 0; k < D; k++)
            acc = fmaf(W7[d * D + k], u_fin[(size_t)v * D + k], acc);
        h = fmaxf(acc, 0.f) * w5[t];
    }
    part[t] = h;
    __syncthreads();
#pragma unroll
    for (int s = 64; s > 0; s >>= 1) {
        if (t < s) part[t] += part[t + s];
        __syncthreads();
    }
    if (t == 0) out[0] = part[0];
}

// ---------------------------------------------------------------------------
extern "C" void kernel_launch(void* const* d_in, const int* in_sizes, int n_in,
                              void* d_out, int out_size) {
    const float* graph  = (const float*)d_in[0];
    const int*   s_mask = (const int*)  d_in[1];
    const int*   v      = (const int*)  d_in[2];
    const float* w1     = (const float*)d_in[3];
    const float* W2     = (const float*)d_in[4];
    const float* W3     = (const float*)d_in[5];
    const float* w4     = (const float*)d_in[6];
    const float* w5     = (const float*)d_in[7];
    const float* W6     = (const float*)d_in[8];
    const float* W7     = (const float*)d_in[9];
    float* out = (float*)d_out;

    k_pre<<<1, 256>>>(W3, w4);
    k_rowsum<<<NN, 256>>>(graph);

    dim3 blk(D, 8);
    // u0 = 0 implicit; u1 = relu(base) -> buf0, s1 -> sums[0]
    k_iter<true><<<256, blk>>>(0, 0, 0, 0, s_mask, w1, W2);
    // u2: buf0 -> buf1, uses s1, writes s2
    k_iter<false><<<256, blk>>>(0, 1, 0, 1, s_mask, w1, W2);
    // u3: buf1 -> buf0, uses s2, writes s3
    k_iter<false><<<256, blk>>>(1, 0, 1, 2, s_mask, w1, W2);
    // u4: buf0 -> buf1, uses s3, writes s4
    k_iter<false><<<256, blk>>>(0, 1, 2, 3, s_mask, w1, W2);

    k_final<<<1, 128>>>(1, 3, v, W6, W7, w5, out);
}